// round 12
// baseline (speedup 1.0000x reference)
#include <cuda_runtime.h>
#include <cstdint>

#define LOCN  10000
#define DLOC  128
#define DST   64
#define DSUM  256
#define BB    64
#define SS    128
#define NIDX  (BB * SS)        // 8192 loc entries (with duplicates)
#define NBLK  296              // 2 blocks/SM x 148 SMs
#define NAUX  32               // blocks that first write st/ed/yt regions

// Final Y = relu(A@W + b)*16 for claimed rows (5.12 MB).
__device__ float g_Y[(size_t)LOCN * DLOC];
__device__ int   g_flag[LOCN];     // epoch-tagged claims (never cleared)
__device__ int   g_work;           // work-stealing cursor over loc entries
__device__ int   g_epoch;          // bumped by gather kernel each launch

// ---------------------------------------------------------------------------
// Kernel 1: row-stealing SpMM (round-8 core + pop prefetch). The LAST NAUX
// blocks first write the Y-independent output regions (st/ed/yt) — overlapped
// with the other 264 blocks' A-streaming — then join the stealing pool.
// ---------------------------------------------------------------------------
__global__ void __launch_bounds__(256, 2) spmm_kernel(
    const int*   __restrict__ loc,
    const int*   __restrict__ st,
    const int*   __restrict__ ed,
    const float* __restrict__ A,
    const float* __restrict__ W,
    const float* __restrict__ bias,
    const float* __restrict__ emb_st,
    const float* __restrict__ emb_ed,
    float4*      __restrict__ out)
{
    const int lane = threadIdx.x & 31;
    const int e    = g_epoch + 1;

    // ---------- Aux blocks: st / ed / yt output regions (overlapped) ------
    if (blockIdx.x >= NBLK - NAUX) {
        constexpr int N1V = NIDX * (DSUM / 4);      // 524288 (res region)
        constexpr int NJ  = NIDX * 48;              // 393216 non-Y float4
        const int atid = (blockIdx.x - (NBLK - NAUX)) * 256 + threadIdx.x;
        const float4* __restrict__ stv = reinterpret_cast<const float4*>(emb_st);
        const float4* __restrict__ edv = reinterpret_cast<const float4*>(emb_ed);
        const float s = 16.0f;

        for (int j = atid; j < NJ; j += NAUX * 256) {
            const int token = j / 48;
            const int k     = j - token * 48;
            if (k < 16) {                       // st branch, d4 = 32+k
                float4 r = stv[st[token] * 16 + k];
                r.x *= s; r.y *= s; r.z *= s; r.w *= s;
                out[token * 64 + 32 + k] = r;
            } else if (k < 32) {                // ed branch
                float4 r = edv[ed[token] * 16 + (k - 16)];
                r.x *= s; r.y *= s; r.z *= s; r.w *= s;
                out[token * 64 + 32 + k] = r;
            } else {                            // yt region (NOT scaled)
                const int kk = k - 32;
                const int ss = token & (SS - 1);
                const int yt = (ss < SS - 1) ? st[token + 1] : 0;
                out[N1V + token * 16 + kk] = stv[yt * 16 + kk];
            }
        }
    }

    // ---------- All blocks: whole-row work stealing with pop prefetch ------
    constexpr int NV4   = LOCN / 4;                    // 2500
    constexpr int K     = 8;                           // float4/lane/iter
    constexpr int VPI   = 32 * K;                      // 256 float4/warp/iter
    constexpr int NITER = (NV4 + VPI - 1) / VPI;       // 10
    const float4 Z = make_float4(0.f, 0.f, 0.f, 0.f);

    const float b0v = bias[lane];
    const float b1v = bias[lane + 32];
    const float b2v = bias[lane + 64];
    const float b3v = bias[lane + 96];

    // lane-0 private prefetched pop state
    int p_widx = NIDX, p_row = 0, p_claimed = 0;
    if (lane == 0) {
        p_widx = atomicAdd(&g_work, 1);
        p_claimed = 0;
        if (p_widx < NIDX) {
            p_row = __ldg(&loc[p_widx]);
            p_claimed = (atomicExch(&g_flag[p_row], e) != e);
        }
    }

    for (;;) {
        const int widx    = __shfl_sync(0xffffffffu, p_widx, 0);
        const int claimed = __shfl_sync(0xffffffffu, p_claimed, 0);
        const int row     = __shfl_sync(0xffffffffu, p_row, 0);
        if (widx >= NIDX) return;

        if (!claimed) {                  // duplicate: synchronous re-pop
            if (lane == 0) {
                p_widx = atomicAdd(&g_work, 1);
                p_claimed = 0;
                if (p_widx < NIDX) {
                    p_row = __ldg(&loc[p_widx]);
                    p_claimed = (atomicExch(&g_flag[p_row], e) != e);
                }
            }
            continue;
        }

        // Prefetch the NEXT pop now; consumed after this row's work.
        if (lane == 0) {
            p_widx = atomicAdd(&g_work, 1);
            p_claimed = 0;
            if (p_widx < NIDX) {
                p_row = __ldg(&loc[p_widx]);
                p_claimed = (atomicExch(&g_flag[p_row], e) != e);
            }
        }

        const float4* __restrict__ rp =
            reinterpret_cast<const float4*>(A + (size_t)row * LOCN);

        float acc0 = 0.f, acc1 = 0.f, acc2 = 0.f, acc3 = 0.f;

        float4 cur[K], nxt[K];
        #pragma unroll
        for (int k = 0; k < K; ++k) {
            const int idx = lane + 32 * k;
            cur[k] = (idx < NV4) ? __ldcs(&rp[idx]) : Z;
        }

        for (int it = 0; it < NITER; ++it) {
            if (it + 1 < NITER) {
                const int nbase = (it + 1) * VPI + lane;
                #pragma unroll
                for (int k = 0; k < K; ++k) {
                    const int idx = nbase + 32 * k;
                    nxt[k] = (idx < NV4) ? __ldcs(&rp[idx]) : Z;
                }
            }

            #pragma unroll
            for (int k = 0; k < K; ++k) {
                const float4 v = cur[k];
                const bool nz = (v.x != 0.f) | (v.y != 0.f) |
                                (v.z != 0.f) | (v.w != 0.f);
                unsigned m = __ballot_sync(0xffffffffu, nz);
                while (m) {
                    const int j = __ffs(m) - 1;
                    m &= m - 1;
                    const float vx = __shfl_sync(0xffffffffu, v.x, j);
                    const float vy = __shfl_sync(0xffffffffu, v.y, j);
                    const float vz = __shfl_sync(0xffffffffu, v.z, j);
                    const float vw = __shfl_sync(0xffffffffu, v.w, j);
                    const int n0 = (it * VPI + k * 32 + j) * 4;

                    const float* __restrict__ Wr = W + (size_t)n0 * DLOC + lane;
                    if (vx != 0.f) {
                        acc0 = fmaf(vx, Wr[0],  acc0);
                        acc1 = fmaf(vx, Wr[32], acc1);
                        acc2 = fmaf(vx, Wr[64], acc2);
                        acc3 = fmaf(vx, Wr[96], acc3);
                    }
                    Wr += DLOC;
                    if (vy != 0.f) {
                        acc0 = fmaf(vy, Wr[0],  acc0);
                        acc1 = fmaf(vy, Wr[32], acc1);
                        acc2 = fmaf(vy, Wr[64], acc2);
                        acc3 = fmaf(vy, Wr[96], acc3);
                    }
                    Wr += DLOC;
                    if (vz != 0.f) {
                        acc0 = fmaf(vz, Wr[0],  acc0);
                        acc1 = fmaf(vz, Wr[32], acc1);
                        acc2 = fmaf(vz, Wr[64], acc2);
                        acc3 = fmaf(vz, Wr[96], acc3);
                    }
                    Wr += DLOC;
                    if (vw != 0.f) {
                        acc0 = fmaf(vw, Wr[0],  acc0);
                        acc1 = fmaf(vw, Wr[32], acc1);
                        acc2 = fmaf(vw, Wr[64], acc2);
                        acc3 = fmaf(vw, Wr[96], acc3);
                    }
                }
            }

            #pragma unroll
            for (int k = 0; k < K; ++k) cur[k] = nxt[k];
        }

        const float s = 16.0f;
        float* __restrict__ y = g_Y + (size_t)row * DLOC + lane;
        y[0]  = fmaxf(acc0 + b0v, 0.f) * s;
        y[32] = fmaxf(acc1 + b1v, 0.f) * s;
        y[64] = fmaxf(acc2 + b2v, 0.f) * s;
        y[96] = fmaxf(acc3 + b3v, 0.f) * s;
    }
}

// ---------------------------------------------------------------------------
// Kernel 2: loc branch only, 4 independent elements per thread (deep MLP):
//   out[token*64 + d4] = Y[loc[token]][d4], d4 in [0,32) float4.
// Also resets bookkeeping for the next launch.
// ---------------------------------------------------------------------------
__global__ void __launch_bounds__(256) gather_loc_kernel(
    const int* __restrict__ loc,
    float4*    __restrict__ out)
{
    constexpr int NLV = NIDX * 32;               // 262144 float4
    constexpr int QTR = NLV / 4;                 // 65536 threads

    const int tid = blockIdx.x * 256 + threadIdx.x;
    if (tid >= QTR) return;

    if (tid == 0) {
        g_epoch = g_epoch + 1;
        g_work  = 0;
    }

    const float4* __restrict__ Yv = reinterpret_cast<const float4*>(g_Y);

    // Issue all 4 index loads, then all 4 gathers (independent chains).
    int bs[4], d4[4];
    size_t off[4];
    #pragma unroll
    for (int h = 0; h < 4; ++h) {
        const int idx = tid + h * QTR;
        bs[h] = idx >> 5;
        d4[h] = idx & 31;
        off[h] = (size_t)__ldg(&loc[bs[h]]) * 32 + d4[h];
    }
    float4 r[4];
    #pragma unroll
    for (int h = 0; h < 4; ++h) r[h] = Yv[off[h]];
    #pragma unroll
    for (int h = 0; h < 4; ++h) out[bs[h] * 64 + d4[h]] = r[h];
}

extern "C" void kernel_launch(void* const* d_in, const int* in_sizes, int n_in,
                              void* d_out, int out_size)
{
    const int*   loc    = (const int*)  d_in[0];
    const int*   st     = (const int*)  d_in[1];
    const int*   ed     = (const int*)  d_in[2];
    const float* A      = (const float*)d_in[3];
    const float* W_loc  = (const float*)d_in[4];
    const float* b_loc  = (const float*)d_in[5];
    const float* emb_st = (const float*)d_in[6];
    const float* emb_ed = (const float*)d_in[7];

    spmm_kernel<<<NBLK, 256>>>(loc, st, ed, A, W_loc, b_loc,
                               emb_st, emb_ed, (float4*)d_out);

    constexpr int qtr = NIDX * 32 / 4;
    gather_loc_kernel<<<qtr / 256, 256>>>(loc, (float4*)d_out);
}

// round 13
// speedup vs baseline: 1.2479x; 1.2479x over previous
#include <cuda_runtime.h>
#include <cstdint>

#define LOCN  10000
#define DLOC  128
#define DST   64
#define DSUM  256
#define BB    64
#define SS    128
#define NIDX  (BB * SS)        // 8192 loc entries (with duplicates)
#define NBLK  296              // 2 blocks/SM x 148 SMs

// Final Y = relu(A@W + b)*16 for claimed rows (5.12 MB).
__device__ float g_Y[(size_t)LOCN * DLOC];
__device__ int   g_flag[LOCN];     // epoch-tagged claims (never cleared)
__device__ int   g_work;           // work-stealing cursor over loc entries
__device__ int   g_epoch;          // bumped by gather kernel each launch

// ---------------------------------------------------------------------------
// Kernel 1: whole-row work-stealing SpMM with inline dedup (round-8 core)
// plus prefetched pops: lane 0 issues the next atomicAdd+claim before
// streaming the current row, hiding the inter-row atomic chain.
// Per row: 8 float4/lane/iter + next-iter prefetch (16 loads in flight).
// ---------------------------------------------------------------------------
__global__ void __launch_bounds__(256, 2) spmm_dedup_kernel(
    const int*   __restrict__ loc,
    const float* __restrict__ A,
    const float* __restrict__ W,
    const float* __restrict__ bias)
{
    const int lane = threadIdx.x & 31;
    const int e    = g_epoch + 1;

    constexpr int NV4   = LOCN / 4;                    // 2500
    constexpr int K     = 8;                           // float4/lane/iter
    constexpr int VPI   = 32 * K;                      // 256 float4/warp/iter
    constexpr int NITER = (NV4 + VPI - 1) / VPI;       // 10
    const float4 Z = make_float4(0.f, 0.f, 0.f, 0.f);

    const float b0v = bias[lane];
    const float b1v = bias[lane + 32];
    const float b2v = bias[lane + 64];
    const float b3v = bias[lane + 96];

    // lane-0 private prefetched pop state.
    int p_widx = NIDX, p_row = 0, p_claimed = 0;
    if (lane == 0) {
        p_widx = atomicAdd(&g_work, 1);
        if (p_widx < NIDX) {
            p_row = __ldg(&loc[p_widx]);
            p_claimed = (atomicExch(&g_flag[p_row], e) != e);
        }
    }

    for (;;) {
        const int widx    = __shfl_sync(0xffffffffu, p_widx, 0);
        const int claimed = __shfl_sync(0xffffffffu, p_claimed, 0);
        const int row     = __shfl_sync(0xffffffffu, p_row, 0);
        if (widx >= NIDX) return;

        if (!claimed) {                  // duplicate: synchronous re-pop
            if (lane == 0) {
                p_widx = atomicAdd(&g_work, 1);
                p_claimed = 0;
                if (p_widx < NIDX) {
                    p_row = __ldg(&loc[p_widx]);
                    p_claimed = (atomicExch(&g_flag[p_row], e) != e);
                }
            }
            continue;
        }

        // Prefetch the NEXT pop; consumed only after this row's work.
        if (lane == 0) {
            p_widx = atomicAdd(&g_work, 1);
            p_claimed = 0;
            if (p_widx < NIDX) {
                p_row = __ldg(&loc[p_widx]);
                p_claimed = (atomicExch(&g_flag[p_row], e) != e);
            }
        }

        const float4* __restrict__ rp =
            reinterpret_cast<const float4*>(A + (size_t)row * LOCN);

        float acc0 = 0.f, acc1 = 0.f, acc2 = 0.f, acc3 = 0.f;

        float4 cur[K], nxt[K];
        #pragma unroll
        for (int k = 0; k < K; ++k) {
            const int idx = lane + 32 * k;
            cur[k] = (idx < NV4) ? __ldcs(&rp[idx]) : Z;
        }

        for (int it = 0; it < NITER; ++it) {
            if (it + 1 < NITER) {
                const int nbase = (it + 1) * VPI + lane;
                #pragma unroll
                for (int k = 0; k < K; ++k) {
                    const int idx = nbase + 32 * k;
                    nxt[k] = (idx < NV4) ? __ldcs(&rp[idx]) : Z;
                }
            }

            #pragma unroll
            for (int k = 0; k < K; ++k) {
                const float4 v = cur[k];
                const bool nz = (v.x != 0.f) | (v.y != 0.f) |
                                (v.z != 0.f) | (v.w != 0.f);
                unsigned m = __ballot_sync(0xffffffffu, nz);
                while (m) {
                    const int j = __ffs(m) - 1;
                    m &= m - 1;
                    const float vx = __shfl_sync(0xffffffffu, v.x, j);
                    const float vy = __shfl_sync(0xffffffffu, v.y, j);
                    const float vz = __shfl_sync(0xffffffffu, v.z, j);
                    const float vw = __shfl_sync(0xffffffffu, v.w, j);
                    const int n0 = (it * VPI + k * 32 + j) * 4;

                    const float* __restrict__ Wr = W + (size_t)n0 * DLOC + lane;
                    if (vx != 0.f) {
                        acc0 = fmaf(vx, Wr[0],  acc0);
                        acc1 = fmaf(vx, Wr[32], acc1);
                        acc2 = fmaf(vx, Wr[64], acc2);
                        acc3 = fmaf(vx, Wr[96], acc3);
                    }
                    Wr += DLOC;
                    if (vy != 0.f) {
                        acc0 = fmaf(vy, Wr[0],  acc0);
                        acc1 = fmaf(vy, Wr[32], acc1);
                        acc2 = fmaf(vy, Wr[64], acc2);
                        acc3 = fmaf(vy, Wr[96], acc3);
                    }
                    Wr += DLOC;
                    if (vz != 0.f) {
                        acc0 = fmaf(vz, Wr[0],  acc0);
                        acc1 = fmaf(vz, Wr[32], acc1);
                        acc2 = fmaf(vz, Wr[64], acc2);
                        acc3 = fmaf(vz, Wr[96], acc3);
                    }
                    Wr += DLOC;
                    if (vw != 0.f) {
                        acc0 = fmaf(vw, Wr[0],  acc0);
                        acc1 = fmaf(vw, Wr[32], acc1);
                        acc2 = fmaf(vw, Wr[64], acc2);
                        acc3 = fmaf(vw, Wr[96], acc3);
                    }
                }
            }

            #pragma unroll
            for (int k = 0; k < K; ++k) cur[k] = nxt[k];
        }

        const float s = 16.0f;
        float* __restrict__ y = g_Y + (size_t)row * DLOC + lane;
        y[0]  = fmaxf(acc0 + b0v, 0.f) * s;
        y[32] = fmaxf(acc1 + b1v, 0.f) * s;
        y[64] = fmaxf(acc2 + b2v, 0.f) * s;
        y[96] = fmaxf(acc3 + b3v, 0.f) * s;
    }
}

// ---------------------------------------------------------------------------
// Kernel 2: full output assembly, ONE float4 per thread, grid 2560 —
// the measured-fastest configuration (parallelism-bound gather).
// Also bumps epoch / resets the cursor for the next launch.
// ---------------------------------------------------------------------------
__global__ void __launch_bounds__(256) gather_concat_kernel(
    const int*   __restrict__ loc,
    const int*   __restrict__ st,
    const int*   __restrict__ ed,
    const float* __restrict__ emb_st,
    const float* __restrict__ emb_ed,
    float4*      __restrict__ out)
{
    constexpr int N1V = BB * SS * DSUM / 4;          // 524288 float4
    constexpr int NTV = N1V + BB * SS * DST / 4;     // 655360 float4

    const int idx = blockIdx.x * blockDim.x + threadIdx.x;
    if (idx >= NTV) return;

    if (idx == 0) {
        g_epoch = g_epoch + 1;
        g_work  = 0;
    }

    const float4* __restrict__ Yv  = reinterpret_cast<const float4*>(g_Y);
    const float4* __restrict__ stv = reinterpret_cast<const float4*>(emb_st);
    const float4* __restrict__ edv = reinterpret_cast<const float4*>(emb_ed);
    const float s = 16.0f;

    float4 r;
    if (idx < N1V) {
        const int bs = idx >> 6;
        const int d4 = idx & 63;
        if (d4 < 32) {                               // loc (pre-scaled)
            r = Yv[(size_t)loc[bs] * 32 + d4];
        } else if (d4 < 48) {                        // st
            r = stv[st[bs] * 16 + (d4 - 32)];
            r.x *= s; r.y *= s; r.z *= s; r.w *= s;
        } else {                                     // ed
            r = edv[ed[bs] * 16 + (d4 - 48)];
            r.x *= s; r.y *= s; r.z *= s; r.w *= s;
        }
    } else {
        const int j  = idx - N1V;
        const int bs = j >> 4;
        const int d4 = j & 15;
        const int ss = bs & (SS - 1);
        const int yt = (ss < SS - 1) ? st[bs + 1] : 0;
        r = stv[yt * 16 + d4];                       // res_yt NOT scaled
    }
    out[idx] = r;
}

extern "C" void kernel_launch(void* const* d_in, const int* in_sizes, int n_in,
                              void* d_out, int out_size)
{
    const int*   loc    = (const int*)  d_in[0];
    const int*   st     = (const int*)  d_in[1];
    const int*   ed     = (const int*)  d_in[2];
    const float* A      = (const float*)d_in[3];
    const float* W_loc  = (const float*)d_in[4];
    const float* b_loc  = (const float*)d_in[5];
    const float* emb_st = (const float*)d_in[6];
    const float* emb_ed = (const float*)d_in[7];

    spmm_dedup_kernel<<<NBLK, 256>>>(loc, A, W_loc, b_loc);

    constexpr int totalv = (BB * SS * DSUM + BB * SS * DST) / 4;
    gather_concat_kernel<<<(totalv + 255) / 256, 256>>>(
        loc, st, ed, emb_st, emb_ed, (float4*)d_out);
}